// round 1
// baseline (speedup 1.0000x reference)
#include <cuda_runtime.h>
#include <math.h>

// Problem constants (fixed by setup_inputs)
#define M_TOK   8192      // B*S = 4*2048
#define IN_F    2048
#define OUT_F   2048
#define NEXP    4
#define RANK    8
#define NJ      (NEXP*RANK)   // 32 rank dims total
#define SCALE   2.0f          // alpha/r = 16/8

// scratch for gate-weighted rank coefficients: coef[t][e*8+r]
__device__ float g_coef[M_TOK * NJ];

// ---------------------------------------------------------------------------
// Kernel 1: router logits + softmax gates + rank projections, fused.
// One warp per token. 36 accumulators/lane, butterfly-reduced.
// ---------------------------------------------------------------------------
__global__ __launch_bounds__(256)
void router_proj_kernel(const float* __restrict__ X,
                        const float* __restrict__ A,     // (E,R,IN_F) = (32, IN_F)
                        const float* __restrict__ Rw,    // (E, IN_F)
                        float* __restrict__ coef)
{
    const int warp  = threadIdx.x >> 5;
    const int lane  = threadIdx.x & 31;
    const int token = blockIdx.x * 8 + warp;
    if (token >= M_TOK) return;

    const float* xrow = X + (size_t)token * IN_F;

    float acc[NJ + NEXP];
    #pragma unroll
    for (int j = 0; j < NJ + NEXP; j++) acc[j] = 0.0f;

    for (int k = lane; k < IN_F; k += 32) {
        const float xv = xrow[k];
        #pragma unroll
        for (int j = 0; j < NJ; j++)
            acc[j] += xv * A[(size_t)j * IN_F + k];
        #pragma unroll
        for (int e = 0; e < NEXP; e++)
            acc[NJ + e] += xv * Rw[(size_t)e * IN_F + k];
    }

    // butterfly reduce all 36 sums -> every lane holds full sums
    #pragma unroll
    for (int off = 16; off > 0; off >>= 1) {
        #pragma unroll
        for (int j = 0; j < NJ + NEXP; j++)
            acc[j] += __shfl_xor_sync(0xffffffffu, acc[j], off);
    }

    // softmax over 4 logits (every lane redundantly; static indices only)
    float l0 = acc[NJ + 0], l1 = acc[NJ + 1], l2 = acc[NJ + 2], l3 = acc[NJ + 3];
    float mx = fmaxf(fmaxf(l0, l1), fmaxf(l2, l3));
    float e0 = __expf(l0 - mx), e1 = __expf(l1 - mx),
          e2 = __expf(l2 - mx), e3 = __expf(l3 - mx);
    float inv = 1.0f / (e0 + e1 + e2 + e3);

    // lane j (j<32) writes coef[t][j] = proj[j] * gate[j/8] * SCALE
    if (lane < NJ) {
        float myproj = 0.0f;
        #pragma unroll
        for (int j = 0; j < NJ; j++)
            if (lane == j) myproj = acc[j];    // static indices -> SEL chain, no spill
        float g = 0.0f;
        int e = lane >> 3;
        if (e == 0) g = e0; else if (e == 1) g = e1; else if (e == 2) g = e2; else g = e3;
        coef[(size_t)token * NJ + lane] = myproj * g * inv * SCALE;
    }
}

// ---------------------------------------------------------------------------
// Kernel 2: fused GEMM
//   out[m][n] = sum_k X[m][k]*W[n][k]  (64 tiles of BK=32)
//            + sum_j coef[m][j]*Bcat[j][n]   (1 extra "K tile" of 32)
//            + bias[n]
// 128x128 block tile, 8x8 per-thread micro-tile, 256 threads.
// ---------------------------------------------------------------------------
#define BM 128
#define BN 128
#define BK 32
#define PAD 4

__global__ __launch_bounds__(256, 2)
void fused_gemm_kernel(const float* __restrict__ X,
                       const float* __restrict__ W,      // (OUT_F, IN_F)
                       const float* __restrict__ bias,   // (OUT_F)
                       const float* __restrict__ Bm,     // (E, OUT_F, R)
                       const float* __restrict__ coef,   // (M_TOK, 32)
                       float* __restrict__ out)
{
    __shared__ float xs[BK][BM + PAD];
    __shared__ float ws[BK][BN + PAD];

    const int tid = threadIdx.x;
    const int tx  = tid & 15;           // 16 col-threads
    const int ty  = tid >> 4;           // 16 row-threads
    const int m0  = blockIdx.y * BM;
    const int n0  = blockIdx.x * BN;

    float acc[8][8];
    #pragma unroll
    for (int i = 0; i < 8; i++)
        #pragma unroll
        for (int j = 0; j < 8; j++) acc[i][j] = 0.0f;

    const int NKT = IN_F / BK;          // 64 main tiles, tile NKT is the LoRA tile

    for (int kt = 0; kt <= NKT; kt++) {
        if (kt < NKT) {
            const int kb = kt * BK;
            #pragma unroll
            for (int r = 0; r < 4; r++) {
                int idx = tid + r * 256;          // 0..1023
                int row = idx >> 3;               // 0..127
                int c4  = (idx & 7) << 2;         // 0,4,..,28
                float4 v = *(const float4*)(X + (size_t)(m0 + row) * IN_F + kb + c4);
                xs[c4+0][row] = v.x; xs[c4+1][row] = v.y;
                xs[c4+2][row] = v.z; xs[c4+3][row] = v.w;
                float4 u = *(const float4*)(W + (size_t)(n0 + row) * IN_F + kb + c4);
                ws[c4+0][row] = u.x; ws[c4+1][row] = u.y;
                ws[c4+2][row] = u.z; ws[c4+3][row] = u.w;
            }
        } else {
            // LoRA tile: xs <- coef (M x 32), ws <- Bcat (32 x N)
            #pragma unroll
            for (int r = 0; r < 4; r++) {
                int idx = tid + r * 256;
                int row = idx >> 3;
                int c4  = (idx & 7) << 2;
                float4 v = *(const float4*)(coef + (size_t)(m0 + row) * NJ + c4);
                xs[c4+0][row] = v.x; xs[c4+1][row] = v.y;
                xs[c4+2][row] = v.z; xs[c4+3][row] = v.w;
            }
            #pragma unroll
            for (int it = 0; it < 16; it++) {
                int idx = tid + it * 256;         // 0..4095
                int j = idx & 31;                 // rank dim
                int n = idx >> 5;                 // 0..127
                int e = j >> 3, rr = j & 7;
                ws[j][n] = Bm[((size_t)e * OUT_F + (n0 + n)) * RANK + rr];
            }
        }
        __syncthreads();

        #pragma unroll
        for (int kk = 0; kk < BK; kk++) {
            float a[8], b[8];
            float4 a0 = *(const float4*)&xs[kk][ty * 8];
            float4 a1 = *(const float4*)&xs[kk][ty * 8 + 4];
            float4 b0 = *(const float4*)&ws[kk][tx * 8];
            float4 b1 = *(const float4*)&ws[kk][tx * 8 + 4];
            a[0]=a0.x; a[1]=a0.y; a[2]=a0.z; a[3]=a0.w;
            a[4]=a1.x; a[5]=a1.y; a[6]=a1.z; a[7]=a1.w;
            b[0]=b0.x; b[1]=b0.y; b[2]=b0.z; b[3]=b0.w;
            b[4]=b1.x; b[5]=b1.y; b[6]=b1.z; b[7]=b1.w;
            #pragma unroll
            for (int i = 0; i < 8; i++)
                #pragma unroll
                for (int j = 0; j < 8; j++)
                    acc[i][j] = fmaf(a[i], b[j], acc[i][j]);
        }
        __syncthreads();
    }

    // epilogue: + bias, write out
    #pragma unroll
    for (int i = 0; i < 8; i++) {
        const int m = m0 + ty * 8 + i;
        float* orow = out + (size_t)m * OUT_F + n0 + tx * 8;
        const float* brow = bias + n0 + tx * 8;
        float4 o0, o1;
        o0.x = acc[i][0] + brow[0]; o0.y = acc[i][1] + brow[1];
        o0.z = acc[i][2] + brow[2]; o0.w = acc[i][3] + brow[3];
        o1.x = acc[i][4] + brow[4]; o1.y = acc[i][5] + brow[5];
        o1.z = acc[i][6] + brow[6]; o1.w = acc[i][7] + brow[7];
        *(float4*)(orow)     = o0;
        *(float4*)(orow + 4) = o1;
    }
}

// ---------------------------------------------------------------------------
extern "C" void kernel_launch(void* const* d_in, const int* in_sizes, int n_in,
                              void* d_out, int out_size)
{
    const float* x      = (const float*)d_in[0];  // (4,2048,2048)
    const float* base_w = (const float*)d_in[1];  // (2048,2048)
    const float* base_b = (const float*)d_in[2];  // (2048)
    const float* A      = (const float*)d_in[3];  // (4,8,2048)
    const float* Bm     = (const float*)d_in[4];  // (4,2048,8)
    const float* rw     = (const float*)d_in[5];  // (4,2048)
    float* out = (float*)d_out;

    float* coef = nullptr;
    cudaGetSymbolAddress((void**)&coef, g_coef);

    // Kernel 1: 8 warps/block, 1 token/warp
    router_proj_kernel<<<M_TOK / 8, 256>>>(x, A, rw, coef);

    // Kernel 2: fused base GEMM + LoRA rank-32 K-extension + bias
    dim3 grid(OUT_F / BN, M_TOK / BM);
    fused_gemm_kernel<<<grid, 256>>>(x, base_w, base_b, Bm, coef, out);
}

// round 3
// speedup vs baseline: 1.2376x; 1.2376x over previous
#include <cuda_runtime.h>
#include <cuda_bf16.h>
#include <cstdint>
#include <math.h>

// ---------------- problem constants ----------------
#define M_TOK   8192
#define IN_F    2048
#define OUT_F   2048
#define NEXP    4
#define RANK    8
#define NJ      32
#define SCALE   2.0f

// extended-K layout: [x_hi(2048) | x_lo(2048) | x_hi(2048) | lora(96)]
#define KSEG    2048
#define KLORA0  6144
#define KEXT    6240

// ---------------- device scratch (static, no allocation) ----------------
__device__ __nv_bfloat16  g_Aext[(size_t)M_TOK * KEXT];
__device__ __nv_bfloat16  g_Bext[(size_t)OUT_F * KEXT];

// ---------------- helpers ----------------
__device__ __forceinline__ uint32_t smem_u32(const void* p) {
    uint32_t a;
    asm("{ .reg .u64 t; cvta.to.shared.u64 t, %1; cvt.u32.u64 %0, t; }" : "=r"(a) : "l"(p));
    return a;
}
__device__ __forceinline__ void cp_async16(uint32_t dst, const void* src) {
    asm volatile("cp.async.cg.shared.global [%0], [%1], 16;" :: "r"(dst), "l"(src) : "memory");
}
__device__ __forceinline__ void cp_commit() {
    asm volatile("cp.async.commit_group;" ::: "memory");
}
__device__ __forceinline__ void ldsm4(uint32_t* r, uint32_t addr) {
    asm volatile("ldmatrix.sync.aligned.m8n8.x4.shared.b16 {%0,%1,%2,%3}, [%4];"
                 : "=r"(r[0]), "=r"(r[1]), "=r"(r[2]), "=r"(r[3]) : "r"(addr));
}
__device__ __forceinline__ void mma_bf16(float* c, const uint32_t* a, uint32_t b0, uint32_t b1) {
    asm volatile("mma.sync.aligned.m16n8k16.row.col.f32.bf16.bf16.f32 "
                 "{%0,%1,%2,%3}, {%4,%5,%6,%7}, {%8,%9}, {%0,%1,%2,%3};"
                 : "+f"(c[0]), "+f"(c[1]), "+f"(c[2]), "+f"(c[3])
                 : "r"(a[0]), "r"(a[1]), "r"(a[2]), "r"(a[3]), "r"(b0), "r"(b1));
}

// ---------------- Kernel 1: router + rank projections -> A_ext LoRA tail ----------------
// 256 threads, 8 tokens/block (1 per warp). A(32 rows)+Rw(4 rows) staged in SMEM
// per 256-wide k-chunk; conflict-free LDS; writes coef hi/lo/hi bf16 directly.
__global__ __launch_bounds__(256)
void router_proj_kernel(const float* __restrict__ X, const float* __restrict__ A,
                        const float* __restrict__ Rw, __nv_bfloat16* __restrict__ Aext)
{
    __shared__ float AR[36 * 256];
    const int tid = threadIdx.x;
    const int warp = tid >> 5, lane = tid & 31;
    const int token = blockIdx.x * 8 + warp;

    float acc[36];
#pragma unroll
    for (int j = 0; j < 36; j++) acc[j] = 0.0f;

    const float* xrow = X + (size_t)token * IN_F;

    for (int c = 0; c < 8; c++) {
        const int k0 = c * 256;
        // cooperative fill: 36 rows x 256 floats = 2304 float4 slots
#pragma unroll
        for (int t = 0; t < 9; t++) {
            int idx = tid + t * 256;
            int row = idx >> 6;
            int c4  = (idx & 63) << 2;
            const float* src = (row < 32) ? (A + (size_t)row * IN_F)
                                          : (Rw + (size_t)(row - 32) * IN_F);
            *(float4*)(AR + row * 256 + c4) = *(const float4*)(src + k0 + c4);
        }
        __syncthreads();

        float xv[8];
#pragma unroll
        for (int kk = 0; kk < 8; kk++) xv[kk] = xrow[k0 + kk * 32 + lane];
#pragma unroll
        for (int kk = 0; kk < 8; kk++) {
            const float* col = AR + kk * 32 + lane;
#pragma unroll
            for (int j = 0; j < 36; j++)
                acc[j] = fmaf(xv[kk], col[j * 256], acc[j]);
        }
        __syncthreads();
    }

    // butterfly reduce all 36 sums
#pragma unroll
    for (int off = 16; off > 0; off >>= 1)
#pragma unroll
        for (int j = 0; j < 36; j++)
            acc[j] += __shfl_xor_sync(0xffffffffu, acc[j], off);

    float l0 = acc[32], l1 = acc[33], l2 = acc[34], l3 = acc[35];
    float mx = fmaxf(fmaxf(l0, l1), fmaxf(l2, l3));
    float e0 = __expf(l0 - mx), e1 = __expf(l1 - mx), e2 = __expf(l2 - mx), e3 = __expf(l3 - mx);
    float inv = 1.0f / (e0 + e1 + e2 + e3);

    float myproj = 0.0f;
#pragma unroll
    for (int j = 0; j < 32; j++) if (lane == j) myproj = acc[j];
    float g = (lane < 8) ? e0 : (lane < 16) ? e1 : (lane < 24) ? e2 : e3;
    float cf = myproj * g * inv * SCALE;

    __nv_bfloat16 h = __float2bfloat16_rn(cf);
    __nv_bfloat16 l = __float2bfloat16_rn(cf - __bfloat162float(h));
    __nv_bfloat16* tail = Aext + (size_t)token * KEXT + KLORA0;
    tail[lane]      = h;
    tail[32 + lane] = l;
    tail[64 + lane] = h;
}

// ---------------- Kernel 2: X -> A_ext [hi|lo|hi] ----------------
__global__ __launch_bounds__(256)
void convert_x_kernel(const float* __restrict__ X, __nv_bfloat16* __restrict__ Aext)
{
    int i = blockIdx.x * 256 + threadIdx.x;
    const int GPR = IN_F / 4;
    int m  = i / GPR;
    int k4 = (i - m * GPR) * 4;
    float4 v = *(const float4*)(X + (size_t)m * IN_F + k4);
    float vv[4] = {v.x, v.y, v.z, v.w};
    __nv_bfloat16 h[4], l[4];
#pragma unroll
    for (int j = 0; j < 4; j++) {
        h[j] = __float2bfloat16_rn(vv[j]);
        l[j] = __float2bfloat16_rn(vv[j] - __bfloat162float(h[j]));
    }
    size_t base = (size_t)m * KEXT + k4;
    __nv_bfloat162 h01; h01.x = h[0]; h01.y = h[1];
    __nv_bfloat162 h23; h23.x = h[2]; h23.y = h[3];
    __nv_bfloat162 l01; l01.x = l[0]; l01.y = l[1];
    __nv_bfloat162 l23; l23.x = l[2]; l23.y = l[3];
    *(__nv_bfloat162*)(Aext + base)              = h01;
    *(__nv_bfloat162*)(Aext + base + 2)          = h23;
    *(__nv_bfloat162*)(Aext + base + KSEG)       = l01;
    *(__nv_bfloat162*)(Aext + base + KSEG + 2)   = l23;
    *(__nv_bfloat162*)(Aext + base + 2*KSEG)     = h01;
    *(__nv_bfloat162*)(Aext + base + 2*KSEG + 2) = h23;
}

// ---------------- Kernel 3: W -> B_ext [hi|hi|lo] ----------------
__global__ __launch_bounds__(256)
void convert_w_kernel(const float* __restrict__ W, __nv_bfloat16* __restrict__ Bext)
{
    int i = blockIdx.x * 256 + threadIdx.x;
    const int GPR = IN_F / 4;
    int n  = i / GPR;
    int k4 = (i - n * GPR) * 4;
    float4 v = *(const float4*)(W + (size_t)n * IN_F + k4);
    float vv[4] = {v.x, v.y, v.z, v.w};
    __nv_bfloat16 h[4], l[4];
#pragma unroll
    for (int j = 0; j < 4; j++) {
        h[j] = __float2bfloat16_rn(vv[j]);
        l[j] = __float2bfloat16_rn(vv[j] - __bfloat162float(h[j]));
    }
    size_t base = (size_t)n * KEXT + k4;
    __nv_bfloat162 h01; h01.x = h[0]; h01.y = h[1];
    __nv_bfloat162 h23; h23.x = h[2]; h23.y = h[3];
    __nv_bfloat162 l01; l01.x = l[0]; l01.y = l[1];
    __nv_bfloat162 l23; l23.x = l[2]; l23.y = l[3];
    *(__nv_bfloat162*)(Bext + base)              = h01;
    *(__nv_bfloat162*)(Bext + base + 2)          = h23;
    *(__nv_bfloat162*)(Bext + base + KSEG)       = h01;
    *(__nv_bfloat162*)(Bext + base + KSEG + 2)   = h23;
    *(__nv_bfloat162*)(Bext + base + 2*KSEG)     = l01;
    *(__nv_bfloat162*)(Bext + base + 2*KSEG + 2) = l23;
}

// ---------------- Kernel 4: Bcat (LoRA B) -> B_ext tail [h|h|l] ----------------
__global__ __launch_bounds__(256)
void bcat_kernel(const float* __restrict__ Bm, __nv_bfloat16* __restrict__ Bext)
{
    int i = blockIdx.x * 256 + threadIdx.x;     // OUT_F * 32
    int n = i >> 5, j = i & 31;
    int e = j >> 3, r = j & 7;
    float b = Bm[((size_t)e * OUT_F + n) * RANK + r];
    __nv_bfloat16 h = __float2bfloat16_rn(b);
    __nv_bfloat16 l = __float2bfloat16_rn(b - __bfloat162float(h));
    __nv_bfloat16* tail = Bext + (size_t)n * KEXT + KLORA0;
    tail[j]      = h;
    tail[32 + j] = h;
    tail[64 + j] = l;
}

// ---------------- Kernel 5: HMMA GEMM 128x256x32, cp.async double-buffered ----------------
#define BMg 128
#define BNg 256
#define BKg 32
#define ASTRIDE 56                       // halves; 112B row stride
#define A_BYTES (BMg * ASTRIDE * 2)      // 14336
#define B_BYTES (BNg * ASTRIDE * 2)      // 28672
#define STAGE_BYTES (A_BYTES + B_BYTES)  // 43008
#define GEMM_SMEM (2 * STAGE_BYTES)      // 86016
#define NKTg (KEXT / BKg)                // 195

__global__ __launch_bounds__(512, 1)
void gemm_hmma_kernel(const __nv_bfloat16* __restrict__ Aext,
                      const __nv_bfloat16* __restrict__ Bext,
                      const float* __restrict__ bias,
                      float* __restrict__ out)
{
    extern __shared__ __align__(128) char smem[];
    const uint32_t s0 = smem_u32(smem);
    const int tid  = threadIdx.x;
    const int wid  = tid >> 5, lane = tid & 31;
    const int wm   = wid >> 2, wn = wid & 3;          // 4x4 warp grid
    const int m0   = blockIdx.y * BMg, n0 = blockIdx.x * BNg;

    // cp.async addressing: 16B chunks; A 512 chunks (1/thread), B 1024 (2/thread)
    const int ldrow = tid >> 2;            // 0..127
    const int ldch  = tid & 3;             // 0..3
    const __nv_bfloat16* a_src  = Aext + (size_t)(m0 + ldrow) * KEXT + ldch * 8;
    const __nv_bfloat16* b_src0 = Bext + (size_t)(n0 + ldrow) * KEXT + ldch * 8;
    const __nv_bfloat16* b_src1 = Bext + (size_t)(n0 + 128 + ldrow) * KEXT + ldch * 8;
    const uint32_t a_dst  = ldrow * 112 + ldch * 16;
    const uint32_t b_dst0 = A_BYTES + ldrow * 112 + ldch * 16;
    const uint32_t b_dst1 = A_BYTES + (128 + ldrow) * 112 + ldch * 16;

    // ldmatrix base offsets (within stage)
    const uint32_t a_lds = (uint32_t)((wm * 32 + (lane & 15)) * 112 + (lane >> 4) * 16);
    const uint32_t b_lds = (uint32_t)(A_BYTES + (wn * 64 + (lane & 15)) * 112 + (lane >> 4) * 16);

    float acc[2][8][4];
#pragma unroll
    for (int i = 0; i < 2; i++)
#pragma unroll
        for (int j = 0; j < 8; j++)
#pragma unroll
            for (int k = 0; k < 4; k++) acc[i][j][k] = 0.0f;

    auto load_tile = [&](int kt, int s) {
        const uint32_t base = s0 + s * STAGE_BYTES;
        const size_t ko = (size_t)kt * BKg;
        cp_async16(base + a_dst,  a_src  + ko);
        cp_async16(base + b_dst0, b_src0 + ko);
        cp_async16(base + b_dst1, b_src1 + ko);
        cp_commit();
    };

    load_tile(0, 0);

    for (int kt = 0; kt < NKTg; kt++) {
        const int s = kt & 1;
        if (kt + 1 < NKTg) {
            load_tile(kt + 1, s ^ 1);
            asm volatile("cp.async.wait_group 1;" ::: "memory");
        } else {
            asm volatile("cp.async.wait_group 0;" ::: "memory");
        }
        __syncthreads();

        const uint32_t abase = s0 + s * STAGE_BYTES + a_lds;
        const uint32_t bbase = s0 + s * STAGE_BYTES + b_lds;
#pragma unroll
        for (int ks = 0; ks < 2; ks++) {
            uint32_t a0[4], a1[4];
            ldsm4(a0, abase + ks * 32);
            ldsm4(a1, abase + 16 * 112 + ks * 32);
            uint32_t b[4][4];
#pragma unroll
            for (int q = 0; q < 4; q++)
                ldsm4(b[q], bbase + q * 16 * 112 + ks * 32);
#pragma unroll
            for (int q = 0; q < 4; q++) {
                mma_bf16(acc[0][2*q],   a0, b[q][0], b[q][2]);
                mma_bf16(acc[0][2*q+1], a0, b[q][1], b[q][3]);
                mma_bf16(acc[1][2*q],   a1, b[q][0], b[q][2]);
                mma_bf16(acc[1][2*q+1], a1, b[q][1], b[q][3]);
            }
        }
        __syncthreads();
    }

    // epilogue: + bias
#pragma unroll
    for (int mf = 0; mf < 2; mf++) {
        const int row = m0 + wm * 32 + mf * 16 + (lane >> 2);
#pragma unroll
        for (int nf = 0; nf < 8; nf++) {
            const int col = n0 + wn * 64 + nf * 8 + (lane & 3) * 2;
            float2 bv = *(const float2*)(bias + col);
            float2 o0, o1;
            o0.x = acc[mf][nf][0] + bv.x; o0.y = acc[mf][nf][1] + bv.y;
            o1.x = acc[mf][nf][2] + bv.x; o1.y = acc[mf][nf][3] + bv.y;
            *(float2*)(out + (size_t)row * OUT_F + col)       = o0;
            *(float2*)(out + (size_t)(row + 8) * OUT_F + col) = o1;
        }
    }
}

// ---------------- host launcher ----------------
extern "C" void kernel_launch(void* const* d_in, const int* in_sizes, int n_in,
                              void* d_out, int out_size)
{
    const float* x      = (const float*)d_in[0];
    const float* base_w = (const float*)d_in[1];
    const float* base_b = (const float*)d_in[2];
    const float* A      = (const float*)d_in[3];
    const float* Bm     = (const float*)d_in[4];
    const float* rw     = (const float*)d_in[5];
    float* out = (float*)d_out;

    __nv_bfloat16 *Aext = nullptr, *Bext = nullptr;
    cudaGetSymbolAddress((void**)&Aext, g_Aext);
    cudaGetSymbolAddress((void**)&Bext, g_Bext);

    static bool attr_set = false;
    if (!attr_set) {
        cudaFuncSetAttribute(gemm_hmma_kernel,
                             cudaFuncAttributeMaxDynamicSharedMemorySize, GEMM_SMEM);
        attr_set = true;
    }

    convert_x_kernel<<<(M_TOK * IN_F / 4) / 256, 256>>>(x, Aext);
    convert_w_kernel<<<(OUT_F * IN_F / 4) / 256, 256>>>(base_w, Bext);
    bcat_kernel<<<(OUT_F * NJ) / 256, 256>>>(Bm, Bext);
    router_proj_kernel<<<M_TOK / 8, 256>>>(x, A, rw, Aext);

    dim3 grid(OUT_F / BNg, M_TOK / BMg);   // (8, 64)
    gemm_hmma_kernel<<<grid, 512, GEMM_SMEM>>>(Aext, Bext, base_b, out);
}

// round 4
// speedup vs baseline: 5.2742x; 4.2615x over previous
#include <cuda_runtime.h>
#include <cuda_fp16.h>
#include <cstdint>
#include <math.h>

// ---------------- problem constants ----------------
#define M_TOK   8192
#define IN_F    2048
#define OUT_F   2048
#define NEXP    4
#define RANK    8
#define NJ      32
#define SCALE   2.0f

// extended-K layout: [x fp16 (2048) | coef fp16 (32)]
#define KEXT    2080
#define KLORA0  2048

// ---------------- device scratch (static, no allocation) ----------------
__device__ __half g_Aext[(size_t)M_TOK * KEXT];
__device__ __half g_Bext[(size_t)OUT_F * KEXT];

// ---------------- helpers ----------------
__device__ __forceinline__ uint32_t smem_u32(const void* p) {
    uint32_t a;
    asm("{ .reg .u64 t; cvta.to.shared.u64 t, %1; cvt.u32.u64 %0, t; }" : "=r"(a) : "l"(p));
    return a;
}
__device__ __forceinline__ void cp_async16(uint32_t dst, const void* src) {
    asm volatile("cp.async.cg.shared.global [%0], [%1], 16;" :: "r"(dst), "l"(src) : "memory");
}
__device__ __forceinline__ void ldsm4(uint32_t* r, uint32_t addr) {
    asm volatile("ldmatrix.sync.aligned.m8n8.x4.shared.b16 {%0,%1,%2,%3}, [%4];"
                 : "=r"(r[0]), "=r"(r[1]), "=r"(r[2]), "=r"(r[3]) : "r"(addr));
}
__device__ __forceinline__ void mma_fp16(float* c, const uint32_t* a, uint32_t b0, uint32_t b1) {
    asm volatile("mma.sync.aligned.m16n8k16.row.col.f32.f16.f16.f32 "
                 "{%0,%1,%2,%3}, {%4,%5,%6,%7}, {%8,%9}, {%0,%1,%2,%3};"
                 : "+f"(c[0]), "+f"(c[1]), "+f"(c[2]), "+f"(c[3])
                 : "r"(a[0]), "r"(a[1]), "r"(a[2]), "r"(a[3]), "r"(b0), "r"(b1));
}

// ---------------- Kernel 1: router + rank projections -> A_ext tail ----------------
// 2 tokens per warp, register-blocked, vectorized float4 LDG (A rows stay hot in L1).
__global__ __launch_bounds__(256)
void router_proj_kernel(const float* __restrict__ X, const float* __restrict__ A,
                        const float* __restrict__ Rw, __half* __restrict__ Aext)
{
    const int warp = threadIdx.x >> 5, lane = threadIdx.x & 31;
    const int t0 = (blockIdx.x * 8 + warp) * 2;
    const int t1 = t0 + 1;

    float acc0[36], acc1[36];
#pragma unroll
    for (int j = 0; j < 36; j++) { acc0[j] = 0.0f; acc1[j] = 0.0f; }

    const float* x0p = X + (size_t)t0 * IN_F;
    const float* x1p = X + (size_t)t1 * IN_F;

    for (int it = 0; it < IN_F / 128; it++) {
        const int k = it * 128 + lane * 4;
        float4 x0 = *(const float4*)(x0p + k);
        float4 x1 = *(const float4*)(x1p + k);
#pragma unroll
        for (int j = 0; j < 32; j++) {
            float4 a4 = *(const float4*)(A + (size_t)j * IN_F + k);
            acc0[j] = fmaf(x0.x, a4.x, fmaf(x0.y, a4.y, fmaf(x0.z, a4.z, fmaf(x0.w, a4.w, acc0[j]))));
            acc1[j] = fmaf(x1.x, a4.x, fmaf(x1.y, a4.y, fmaf(x1.z, a4.z, fmaf(x1.w, a4.w, acc1[j]))));
        }
#pragma unroll
        for (int e = 0; e < 4; e++) {
            float4 a4 = *(const float4*)(Rw + (size_t)e * IN_F + k);
            acc0[32+e] = fmaf(x0.x, a4.x, fmaf(x0.y, a4.y, fmaf(x0.z, a4.z, fmaf(x0.w, a4.w, acc0[32+e]))));
            acc1[32+e] = fmaf(x1.x, a4.x, fmaf(x1.y, a4.y, fmaf(x1.z, a4.z, fmaf(x1.w, a4.w, acc1[32+e]))));
        }
    }

#pragma unroll
    for (int off = 16; off > 0; off >>= 1) {
#pragma unroll
        for (int j = 0; j < 36; j++) {
            acc0[j] += __shfl_xor_sync(0xffffffffu, acc0[j], off);
            acc1[j] += __shfl_xor_sync(0xffffffffu, acc1[j], off);
        }
    }

    // token 0
    {
        float l0 = acc0[32], l1 = acc0[33], l2 = acc0[34], l3 = acc0[35];
        float mx = fmaxf(fmaxf(l0, l1), fmaxf(l2, l3));
        float e0 = __expf(l0-mx), e1 = __expf(l1-mx), e2 = __expf(l2-mx), e3 = __expf(l3-mx);
        float inv = 1.0f / (e0 + e1 + e2 + e3);
        float myproj = 0.0f;
#pragma unroll
        for (int j = 0; j < 32; j++) if (lane == j) myproj = acc0[j];
        float g = (lane < 8) ? e0 : (lane < 16) ? e1 : (lane < 24) ? e2 : e3;
        Aext[(size_t)t0 * KEXT + KLORA0 + lane] = __float2half_rn(myproj * g * inv * SCALE);
    }
    // token 1
    {
        float l0 = acc1[32], l1 = acc1[33], l2 = acc1[34], l3 = acc1[35];
        float mx = fmaxf(fmaxf(l0, l1), fmaxf(l2, l3));
        float e0 = __expf(l0-mx), e1 = __expf(l1-mx), e2 = __expf(l2-mx), e3 = __expf(l3-mx);
        float inv = 1.0f / (e0 + e1 + e2 + e3);
        float myproj = 0.0f;
#pragma unroll
        for (int j = 0; j < 32; j++) if (lane == j) myproj = acc1[j];
        float g = (lane < 8) ? e0 : (lane < 16) ? e1 : (lane < 24) ? e2 : e3;
        Aext[(size_t)t1 * KEXT + KLORA0 + lane] = __float2half_rn(myproj * g * inv * SCALE);
    }
}

// ---------------- Kernel 2: X -> A_ext fp16 ----------------
__global__ __launch_bounds__(256)
void convert_x_kernel(const float* __restrict__ X, __half* __restrict__ Aext)
{
    int i = blockIdx.x * 256 + threadIdx.x;
    const int GPR = IN_F / 4;
    int m  = i / GPR;
    int k4 = (i - m * GPR) * 4;
    float4 v = *(const float4*)(X + (size_t)m * IN_F + k4);
    __half2 h01 = __floats2half2_rn(v.x, v.y);
    __half2 h23 = __floats2half2_rn(v.z, v.w);
    size_t base = (size_t)m * KEXT + k4;
    *(__half2*)(Aext + base)     = h01;
    *(__half2*)(Aext + base + 2) = h23;
}

// ---------------- Kernel 3: W -> B_ext fp16 ----------------
__global__ __launch_bounds__(256)
void convert_w_kernel(const float* __restrict__ W, __half* __restrict__ Bext)
{
    int i = blockIdx.x * 256 + threadIdx.x;
    const int GPR = IN_F / 4;
    int n  = i / GPR;
    int k4 = (i - n * GPR) * 4;
    float4 v = *(const float4*)(W + (size_t)n * IN_F + k4);
    __half2 h01 = __floats2half2_rn(v.x, v.y);
    __half2 h23 = __floats2half2_rn(v.z, v.w);
    size_t base = (size_t)n * KEXT + k4;
    *(__half2*)(Bext + base)     = h01;
    *(__half2*)(Bext + base + 2) = h23;
}

// ---------------- Kernel 4: Bcat (LoRA B) -> B_ext tail ----------------
__global__ __launch_bounds__(256)
void bcat_kernel(const float* __restrict__ Bm, __half* __restrict__ Bext)
{
    int i = blockIdx.x * 256 + threadIdx.x;     // OUT_F * 32
    int n = i >> 5, j = i & 31;
    int e = j >> 3, r = j & 7;
    float b = Bm[((size_t)e * OUT_F + n) * RANK + r];
    Bext[(size_t)n * KEXT + KLORA0 + j] = __float2half_rn(b);
}

// ---------------- Kernel 5: fp16 HMMA GEMM 128x128x32, 3-stage cp.async ----------------
#define BMg 128
#define BNg 128
#define BKg 32
#define RSTRIDE 80                        // 64B data + 16B pad: conflict-free ldsm
#define A_BYTES (BMg * RSTRIDE)           // 10240
#define STAGE_BYTES (2 * A_BYTES)         // 20480 (A then B)
#define NSTAGE 3
#define GEMM_SMEM (NSTAGE * STAGE_BYTES)  // 61440
#define NKTg (KEXT / BKg)                 // 65

__global__ __launch_bounds__(256, 2)
void gemm_hmma_kernel(const __half* __restrict__ Aext,
                      const __half* __restrict__ Bext,
                      const float* __restrict__ bias,
                      float* __restrict__ out)
{
    extern __shared__ __align__(128) char smem[];
    const uint32_t s0 = smem_u32(smem);
    const int tid  = threadIdx.x;
    const int wid  = tid >> 5, lane = tid & 31;
    const int wm   = wid >> 1, wn = wid & 1;           // 4x2 warp grid, 32x64 tiles
    const int m0   = blockIdx.y * BMg, n0 = blockIdx.x * BNg;

    // cp.async addressing: 2 chunks/thread for A, 2 for B
    const int ldrow0 = tid >> 2;            // 0..63
    const int ldrow1 = ldrow0 + 64;         // 64..127
    const int ldch   = tid & 3;
    const __half* a_src0 = Aext + (size_t)(m0 + ldrow0) * KEXT + ldch * 8;
    const __half* a_src1 = Aext + (size_t)(m0 + ldrow1) * KEXT + ldch * 8;
    const __half* b_src0 = Bext + (size_t)(n0 + ldrow0) * KEXT + ldch * 8;
    const __half* b_src1 = Bext + (size_t)(n0 + ldrow1) * KEXT + ldch * 8;
    const uint32_t a_dst0 = ldrow0 * RSTRIDE + ldch * 16;
    const uint32_t a_dst1 = ldrow1 * RSTRIDE + ldch * 16;
    const uint32_t b_dst0 = A_BYTES + ldrow0 * RSTRIDE + ldch * 16;
    const uint32_t b_dst1 = A_BYTES + ldrow1 * RSTRIDE + ldch * 16;

    // ldmatrix bases within a stage
    const uint32_t a_lds = (uint32_t)((wm * 32 + (lane & 15)) * RSTRIDE + (lane >> 4) * 16);
    const uint32_t b_lds = (uint32_t)(A_BYTES + (wn * 64 + (lane & 15)) * RSTRIDE + (lane >> 4) * 16);

    float acc[2][8][4];
#pragma unroll
    for (int i = 0; i < 2; i++)
#pragma unroll
        for (int j = 0; j < 8; j++)
#pragma unroll
            for (int k = 0; k < 4; k++) acc[i][j][k] = 0.0f;

    auto load_tile = [&](int kt, int s) {
        const uint32_t base = s0 + s * STAGE_BYTES;
        const size_t ko = (size_t)kt * BKg;
        cp_async16(base + a_dst0, a_src0 + ko);
        cp_async16(base + a_dst1, a_src1 + ko);
        cp_async16(base + b_dst0, b_src0 + ko);
        cp_async16(base + b_dst1, b_src1 + ko);
        asm volatile("cp.async.commit_group;" ::: "memory");
    };

    load_tile(0, 0);
    load_tile(1, 1);

    for (int kt = 0; kt < NKTg; kt++) {
        const int s = kt % NSTAGE;
        asm volatile("cp.async.wait_group 1;" ::: "memory");
        __syncthreads();

        if (kt + 2 < NKTg) load_tile(kt + 2, (kt + 2) % NSTAGE);

        const uint32_t abase = s0 + s * STAGE_BYTES + a_lds;
        const uint32_t bbase = s0 + s * STAGE_BYTES + b_lds;
#pragma unroll
        for (int ks = 0; ks < 2; ks++) {
            uint32_t a0[4], a1[4];
            ldsm4(a0, abase + ks * 32);
            ldsm4(a1, abase + 16 * RSTRIDE + ks * 32);
            uint32_t b[4][4];
#pragma unroll
            for (int q = 0; q < 4; q++)
                ldsm4(b[q], bbase + q * 16 * RSTRIDE + ks * 32);
#pragma unroll
            for (int q = 0; q < 4; q++) {
                mma_fp16(acc[0][2*q],   a0, b[q][0], b[q][2]);
                mma_fp16(acc[0][2*q+1], a0, b[q][1], b[q][3]);
                mma_fp16(acc[1][2*q],   a1, b[q][0], b[q][2]);
                mma_fp16(acc[1][2*q+1], a1, b[q][1], b[q][3]);
            }
        }
        __syncthreads();
    }

    // epilogue: + bias
#pragma unroll
    for (int mf = 0; mf < 2; mf++) {
        const int row = m0 + wm * 32 + mf * 16 + (lane >> 2);
#pragma unroll
        for (int nf = 0; nf < 8; nf++) {
            const int col = n0 + wn * 64 + nf * 8 + (lane & 3) * 2;
            float2 bv = *(const float2*)(bias + col);
            float2 o0, o1;
            o0.x = acc[mf][nf][0] + bv.x; o0.y = acc[mf][nf][1] + bv.y;
            o1.x = acc[mf][nf][2] + bv.x; o1.y = acc[mf][nf][3] + bv.y;
            *(float2*)(out + (size_t)row * OUT_F + col)       = o0;
            *(float2*)(out + (size_t)(row + 8) * OUT_F + col) = o1;
        }
    }
}

// ---------------- host launcher ----------------
extern "C" void kernel_launch(void* const* d_in, const int* in_sizes, int n_in,
                              void* d_out, int out_size)
{
    const float* x      = (const float*)d_in[0];
    const float* base_w = (const float*)d_in[1];
    const float* base_b = (const float*)d_in[2];
    const float* A      = (const float*)d_in[3];
    const float* Bm     = (const float*)d_in[4];
    const float* rw     = (const float*)d_in[5];
    float* out = (float*)d_out;

    __half *Aext = nullptr, *Bext = nullptr;
    cudaGetSymbolAddress((void**)&Aext, g_Aext);
    cudaGetSymbolAddress((void**)&Bext, g_Bext);

    static bool attr_set = false;
    if (!attr_set) {
        cudaFuncSetAttribute(gemm_hmma_kernel,
                             cudaFuncAttributeMaxDynamicSharedMemorySize, GEMM_SMEM);
        attr_set = true;
    }

    convert_x_kernel<<<(M_TOK * IN_F / 4) / 256, 256>>>(x, Aext);
    convert_w_kernel<<<(OUT_F * IN_F / 4) / 256, 256>>>(base_w, Bext);
    bcat_kernel<<<(OUT_F * NJ) / 256, 256>>>(Bm, Bext);
    router_proj_kernel<<<M_TOK / 16, 256>>>(x, A, rw, Aext);

    dim3 grid(OUT_F / BNg, M_TOK / BMg);   // (16, 64) = 1024 CTAs
    gemm_hmma_kernel<<<grid, 256, GEMM_SMEM>>>(Aext, Bext, base_b, out);
}

// round 5
// speedup vs baseline: 7.8418x; 1.4868x over previous
#include <cuda_runtime.h>
#include <cuda_fp16.h>
#include <cstdint>
#include <math.h>

// ---------------- problem constants ----------------
#define M_TOK   8192
#define IN_F    2048
#define OUT_F   2048
#define NEXP    4
#define RANK    8
#define NJ      32
#define SCALE   2.0f

// extended-K layout: [x fp16 (2048) | coef fp16 (32) | zero pad (32)]
#define KLORA0  2048
#define KEXT    2112            // 33 tiles of 64

// ---------------- device scratch (static, no allocation) ----------------
__device__ __align__(128) __half g_Aext[(size_t)M_TOK * KEXT];
__device__ __align__(128) __half g_Bext[(size_t)OUT_F * KEXT];
__device__ __align__(128) __half g_Wr[64 * IN_F];     // router+proj weights, padded to 64 rows

// ---------------- helpers ----------------
__device__ __forceinline__ uint32_t smem_u32(const void* p) {
    uint32_t a;
    asm("{ .reg .u64 t; cvta.to.shared.u64 t, %1; cvt.u32.u64 %0, t; }" : "=r"(a) : "l"(p));
    return a;
}
__device__ __forceinline__ uint32_t sw128(uint32_t off) { return off ^ ((off >> 3) & 0x70); }
__device__ __forceinline__ void cp_async16(uint32_t dst, const void* src) {
    asm volatile("cp.async.cg.shared.global [%0], [%1], 16;" :: "r"(dst), "l"(src) : "memory");
}
__device__ __forceinline__ void cp_commit() {
    asm volatile("cp.async.commit_group;" ::: "memory");
}
__device__ __forceinline__ void ldsm4(uint32_t* r, uint32_t addr) {
    asm volatile("ldmatrix.sync.aligned.m8n8.x4.shared.b16 {%0,%1,%2,%3}, [%4];"
                 : "=r"(r[0]), "=r"(r[1]), "=r"(r[2]), "=r"(r[3]) : "r"(addr));
}
__device__ __forceinline__ void mma_fp16(float* c, const uint32_t* a, uint32_t b0, uint32_t b1) {
    asm volatile("mma.sync.aligned.m16n8k16.row.col.f32.f16.f16.f32 "
                 "{%0,%1,%2,%3}, {%4,%5,%6,%7}, {%8,%9}, {%0,%1,%2,%3};"
                 : "+f"(c[0]), "+f"(c[1]), "+f"(c[2]), "+f"(c[3])
                 : "r"(a[0]), "r"(a[1]), "r"(a[2]), "r"(a[3]), "r"(b0), "r"(b1));
}

// ---------------- Kernel: X -> A_ext fp16 ----------------
__global__ __launch_bounds__(256)
void convert_x_kernel(const float* __restrict__ X, __half* __restrict__ Aext)
{
    int i = blockIdx.x * 256 + threadIdx.x;
    const int GPR = IN_F / 4;
    int m  = i / GPR;
    int k4 = (i - m * GPR) * 4;
    float4 v = *(const float4*)(X + (size_t)m * IN_F + k4);
    __half2 h01 = __floats2half2_rn(v.x, v.y);
    __half2 h23 = __floats2half2_rn(v.z, v.w);
    size_t base = (size_t)m * KEXT + k4;
    *(__half2*)(Aext + base)     = h01;
    *(__half2*)(Aext + base + 2) = h23;
}

// ---------------- Kernel: W -> B_ext fp16 ----------------
__global__ __launch_bounds__(256)
void convert_w_kernel(const float* __restrict__ W, __half* __restrict__ Bext)
{
    int i = blockIdx.x * 256 + threadIdx.x;
    const int GPR = IN_F / 4;
    int n  = i / GPR;
    int k4 = (i - n * GPR) * 4;
    float4 v = *(const float4*)(W + (size_t)n * IN_F + k4);
    __half2 h01 = __floats2half2_rn(v.x, v.y);
    __half2 h23 = __floats2half2_rn(v.z, v.w);
    size_t base = (size_t)n * KEXT + k4;
    *(__half2*)(Bext + base)     = h01;
    *(__half2*)(Bext + base + 2) = h23;
}

// ---------------- Kernel: Bcat + zero-pad -> B_ext tail ----------------
__global__ __launch_bounds__(256)
void bcat_kernel(const float* __restrict__ Bm, __half* __restrict__ Bext)
{
    int i = blockIdx.x * 256 + threadIdx.x;     // OUT_F * 64
    int n = i >> 6, j = i & 63;
    float b = 0.0f;
    if (j < NJ) {
        int e = j >> 3, r = j & 7;
        b = Bm[((size_t)e * OUT_F + n) * RANK + r];
    }
    Bext[(size_t)n * KEXT + KLORA0 + j] = __float2half_rn(b);
}

// ---------------- Kernel: pack [A(32) | Rw(4) | zeros(28)] -> Wr fp16 ----------------
__global__ __launch_bounds__(256)
void wr_pack_kernel(const float* __restrict__ A, const float* __restrict__ Rw,
                    __half* __restrict__ Wr)
{
    int i = blockIdx.x * 256 + threadIdx.x;        // 64*2048/4 = 32768
    int row = i >> 9;                              // /512
    int k4  = (i & 511) * 4;
    float4 v = make_float4(0.f, 0.f, 0.f, 0.f);
    if (row < 32)      v = *(const float4*)(A  + (size_t)row * IN_F + k4);
    else if (row < 36) v = *(const float4*)(Rw + (size_t)(row - 32) * IN_F + k4);
    __half2 h01 = __floats2half2_rn(v.x, v.y);
    __half2 h23 = __floats2half2_rn(v.z, v.w);
    size_t base = (size_t)row * IN_F + k4;
    *(__half2*)(Wr + base)     = h01;
    *(__half2*)(Wr + base + 2) = h23;
}

// ---------------- Router GEMM: P = Xfp16(8192x2048) @ Wr^T(64x2048) ----------------
// BM=64, N=64, BK=64, 4 warps (each 16x64). Softmax + gating in epilogue,
// writes coef + zero-pad fp16 directly into A_ext tail.
#define RT_NKT (IN_F / 64)      // 32

__global__ __launch_bounds__(128, 2)
void router_gemm_kernel(const __half* __restrict__ Aext,
                        const __half* __restrict__ Wr,
                        __half* __restrict__ AextW)
{
    __shared__ __align__(128) char smem[2 * 16384];
    const uint32_t s0 = smem_u32(smem);
    const int tid = threadIdx.x;
    const int w = tid >> 5, lane = tid & 31;
    const int m0 = blockIdx.x * 64;

    // loader: A 64 rows x 8 chunks = 512; B 64 x 8 = 512; 128 threads -> 4+4 each
    const int lrow = tid >> 3;       // 0..15
    const int lch  = tid & 7;
    uint32_t dstA[4], dstB[4];
    const __half* srcA[4]; const __half* srcB[4];
#pragma unroll
    for (int r = 0; r < 4; r++) {
        int row = lrow + 16 * r;
        dstA[r] = sw128(row * 128 + lch * 16);
        dstB[r] = 8192 + sw128(row * 128 + lch * 16);
        srcA[r] = Aext + (size_t)(m0 + row) * KEXT + lch * 8;
        srcB[r] = Wr + (size_t)row * IN_F + lch * 8;
    }

    auto load_tile = [&](int kt, int s) {
        const uint32_t base = s0 + s * 16384;
        const int ko = kt * 64;
#pragma unroll
        for (int r = 0; r < 4; r++) {
            cp_async16(base + dstA[r], srcA[r] + ko);
            cp_async16(base + dstB[r], srcB[r] + ko);
        }
        cp_commit();
    };

    float acc[8][4];
#pragma unroll
    for (int j = 0; j < 8; j++)
#pragma unroll
        for (int k = 0; k < 4; k++) acc[j][k] = 0.0f;

    load_tile(0, 0);
    load_tile(1, 1);

    const int arow = w * 16 + (lane & 15);
    const int brow = lane & 15;
    const int chsel = lane >> 4;

    for (int kt = 0; kt < RT_NKT; kt++) {
        const int s = kt & 1;
        if (kt + 1 < RT_NKT) asm volatile("cp.async.wait_group 1;" ::: "memory");
        else                 asm volatile("cp.async.wait_group 0;" ::: "memory");
        __syncthreads();

        const uint32_t base = s0 + s * 16384;
#pragma unroll
        for (int ks = 0; ks < 4; ks++) {
            const int ch = ks * 2 + chsel;
            uint32_t a[4];
            ldsm4(a, base + sw128(arow * 128 + ch * 16));
            uint32_t b[4][4];
#pragma unroll
            for (int q = 0; q < 4; q++)
                ldsm4(b[q], base + 8192 + sw128((q * 16 + brow) * 128 + ch * 16));
#pragma unroll
            for (int q = 0; q < 4; q++) {
                mma_fp16(acc[2*q],   a, b[q][0], b[q][2]);
                mma_fp16(acc[2*q+1], a, b[q][1], b[q][3]);
            }
        }
        __syncthreads();
        if (kt + 2 < RT_NKT) load_tile(kt + 2, s);
    }

    // ---- epilogue: softmax over logits (cols 32..35), gate, write coef tail ----
    const int qbase = lane & ~3;
    // row r1 = lane>>2, row r2 = r1+8 within warp tile
    float La0 = __shfl_sync(0xffffffffu, acc[4][0], qbase);
    float La1 = __shfl_sync(0xffffffffu, acc[4][1], qbase);
    float Lb0 = __shfl_sync(0xffffffffu, acc[4][0], qbase | 1);
    float Lb1 = __shfl_sync(0xffffffffu, acc[4][1], qbase | 1);
    float Ma0 = __shfl_sync(0xffffffffu, acc[4][2], qbase);
    float Ma1 = __shfl_sync(0xffffffffu, acc[4][3], qbase);
    float Mb0 = __shfl_sync(0xffffffffu, acc[4][2], qbase | 1);
    float Mb1 = __shfl_sync(0xffffffffu, acc[4][3], qbase | 1);

    float g1[4], g2[4];
    {
        float mx = fmaxf(fmaxf(La0, La1), fmaxf(Lb0, Lb1));
        float e0 = __expf(La0 - mx), e1 = __expf(La1 - mx),
              e2 = __expf(Lb0 - mx), e3 = __expf(Lb1 - mx);
        float s = SCALE / (e0 + e1 + e2 + e3);
        g1[0] = e0 * s; g1[1] = e1 * s; g1[2] = e2 * s; g1[3] = e3 * s;
    }
    {
        float mx = fmaxf(fmaxf(Ma0, Ma1), fmaxf(Mb0, Mb1));
        float e0 = __expf(Ma0 - mx), e1 = __expf(Ma1 - mx),
              e2 = __expf(Mb0 - mx), e3 = __expf(Mb1 - mx);
        float s = SCALE / (e0 + e1 + e2 + e3);
        g2[0] = e0 * s; g2[1] = e1 * s; g2[2] = e2 * s; g2[3] = e3 * s;
    }

    const int t1 = m0 + w * 16 + (lane >> 2);
    const int t2 = t1 + 8;
    __half* tail1 = AextW + (size_t)t1 * KEXT + KLORA0;
    __half* tail2 = AextW + (size_t)t2 * KEXT + KLORA0;
    const int jq = (lane & 3) * 2;
#pragma unroll
    for (int nf = 0; nf < 4; nf++) {
        int j = nf * 8 + jq;
        *(__half2*)(tail1 + j) = __floats2half2_rn(acc[nf][0] * g1[nf], acc[nf][1] * g1[nf]);
        *(__half2*)(tail2 + j) = __floats2half2_rn(acc[nf][2] * g2[nf], acc[nf][3] * g2[nf]);
    }
    __half2 z; z.x = __float2half_rn(0.f); z.y = z.x;
#pragma unroll
    for (int nf = 4; nf < 8; nf++) {
        int j = nf * 8 + jq;
        *(__half2*)(tail1 + j) = z;
        *(__half2*)(tail2 + j) = z;
    }
}

// ---------------- Main GEMM: 128x128x64, SW128 swizzle, 2-stage, 2 CTA/SM ----------------
#define BMg 128
#define BNg 128
#define BKg 64
#define A_BYTES 16384                     // 128 rows x 128B
#define STAGE_BYTES 32768
#define GEMM_SMEM (2 * STAGE_BYTES)       // 65536
#define NKTg (KEXT / BKg)                 // 33

__global__ __launch_bounds__(256, 2)
void gemm_hmma_kernel(const __half* __restrict__ Aext,
                      const __half* __restrict__ Bext,
                      const float* __restrict__ bias,
                      float* __restrict__ out)
{
    extern __shared__ __align__(128) char smem[];
    const uint32_t s0 = smem_u32(smem);
    const int tid  = threadIdx.x;
    const int wid  = tid >> 5, lane = tid & 31;
    const int wm   = wid >> 1, wn = wid & 1;       // 4x2 grid, 32x64 warp tiles
    const int m0   = blockIdx.y * BMg, n0 = blockIdx.x * BNg;

    // loader: A 128x8 chunks + B 128x8 = 2048 chunks, 256 threads -> 4+4 each
    const int lrow = tid >> 3;       // 0..31
    const int lch  = tid & 7;
    uint32_t dstA[4], dstB[4];
    const __half* srcA[4]; const __half* srcB[4];
#pragma unroll
    for (int r = 0; r < 4; r++) {
        int row = lrow + 32 * r;
        dstA[r] = sw128(row * 128 + lch * 16);
        dstB[r] = A_BYTES + sw128(row * 128 + lch * 16);
        srcA[r] = Aext + (size_t)(m0 + row) * KEXT + lch * 8;
        srcB[r] = Bext + (size_t)(n0 + row) * KEXT + lch * 8;
    }

    auto load_tile = [&](int kt, int s) {
        const uint32_t base = s0 + s * STAGE_BYTES;
        const int ko = kt * BKg;
#pragma unroll
        for (int r = 0; r < 4; r++) {
            cp_async16(base + dstA[r], srcA[r] + ko);
            cp_async16(base + dstB[r], srcB[r] + ko);
        }
        cp_commit();
    };

    float acc[2][8][4];
#pragma unroll
    for (int i = 0; i < 2; i++)
#pragma unroll
        for (int j = 0; j < 8; j++)
#pragma unroll
            for (int k = 0; k < 4; k++) acc[i][j][k] = 0.0f;

    load_tile(0, 0);
    load_tile(1, 1);

    const int arow0 = wm * 32 + (lane & 15);
    const int brow  = wn * 64 + (lane & 15);
    const int chsel = lane >> 4;

    for (int kt = 0; kt < NKTg; kt++) {
        const int s = kt & 1;
        if (kt + 1 < NKTg) asm volatile("cp.async.wait_group 1;" ::: "memory");
        else               asm volatile("cp.async.wait_group 0;" ::: "memory");
        __syncthreads();

        const uint32_t base = s0 + s * STAGE_BYTES;
#pragma unroll
        for (int ks = 0; ks < 4; ks++) {
            const int ch = ks * 2 + chsel;
            uint32_t a0[4], a1[4];
            ldsm4(a0, base + sw128(arow0 * 128 + ch * 16));
            ldsm4(a1, base + sw128((arow0 + 16) * 128 + ch * 16));
            uint32_t b[4][4];
#pragma unroll
            for (int q = 0; q < 4; q++)
                ldsm4(b[q], base + A_BYTES + sw128((brow + q * 16) * 128 + ch * 16));
#pragma unroll
            for (int q = 0; q < 4; q++) {
                mma_fp16(acc[0][2*q],   a0, b[q][0], b[q][2]);
                mma_fp16(acc[0][2*q+1], a0, b[q][1], b[q][3]);
                mma_fp16(acc[1][2*q],   a1, b[q][0], b[q][2]);
                mma_fp16(acc[1][2*q+1], a1, b[q][1], b[q][3]);
            }
        }
        __syncthreads();
        if (kt + 2 < NKTg) load_tile(kt + 2, s);
    }

    // epilogue: + bias
#pragma unroll
    for (int mf = 0; mf < 2; mf++) {
        const int row = m0 + wm * 32 + mf * 16 + (lane >> 2);
#pragma unroll
        for (int nf = 0; nf < 8; nf++) {
            const int col = n0 + wn * 64 + nf * 8 + (lane & 3) * 2;
            float2 bv = *(const float2*)(bias + col);
            float2 o0, o1;
            o0.x = acc[mf][nf][0] + bv.x; o0.y = acc[mf][nf][1] + bv.y;
            o1.x = acc[mf][nf][2] + bv.x; o1.y = acc[mf][nf][3] + bv.y;
            *(float2*)(out + (size_t)row * OUT_F + col)       = o0;
            *(float2*)(out + (size_t)(row + 8) * OUT_F + col) = o1;
        }
    }
}

// ---------------- host launcher ----------------
extern "C" void kernel_launch(void* const* d_in, const int* in_sizes, int n_in,
                              void* d_out, int out_size)
{
    const float* x      = (const float*)d_in[0];
    const float* base_w = (const float*)d_in[1];
    const float* base_b = (const float*)d_in[2];
    const float* A      = (const float*)d_in[3];
    const float* Bm     = (const float*)d_in[4];
    const float* rw     = (const float*)d_in[5];
    float* out = (float*)d_out;

    __half *Aext = nullptr, *Bext = nullptr, *Wr = nullptr;
    cudaGetSymbolAddress((void**)&Aext, g_Aext);
    cudaGetSymbolAddress((void**)&Bext, g_Bext);
    cudaGetSymbolAddress((void**)&Wr,   g_Wr);

    static bool attr_set = false;
    if (!attr_set) {
        cudaFuncSetAttribute(gemm_hmma_kernel,
                             cudaFuncAttributeMaxDynamicSharedMemorySize, GEMM_SMEM);
        attr_set = true;
    }

    convert_x_kernel<<<(M_TOK * IN_F / 4) / 256, 256>>>(x, Aext);
    wr_pack_kernel<<<(64 * IN_F / 4) / 256, 256>>>(A, rw, Wr);
    convert_w_kernel<<<(OUT_F * IN_F / 4) / 256, 256>>>(base_w, Bext);
    bcat_kernel<<<(OUT_F * 64) / 256, 256>>>(Bm, Bext);

    router_gemm_kernel<<<M_TOK / 64, 128>>>(Aext, Wr, Aext);

    dim3 grid(OUT_F / BNg, M_TOK / BMg);   // (16, 64) = 1024 CTAs
    gemm_hmma_kernel<<<grid, 256, GEMM_SMEM>>>(Aext, Bext, base_b, out);
}